// round 12
// baseline (speedup 1.0000x reference)
#include <cuda_runtime.h>
#include <cuda_bf16.h>
#include <math.h>

// ---------------- problem constants ----------------
#define DMODEL 1024
#define HEADS  16
#define DH     64
#define B_LAT  9
#define B_X    8
#define N_KV   256
#define N_Q    64
#define CHUNK  (N_KV + N_Q)          // 320
#define KV_ROWS (B_X * CHUNK)        // 2560
#define Q_ROWS  (B_LAT * N_Q)        // 576
#define SCALE   0.125f               // DH^-0.5 applied to Q

// ---------------- scratch ----------------
__device__ float g_kvin[KV_ROWS * DMODEL];
__device__ float g_latn[Q_ROWS * DMODEL];
__device__ float g_Q   [Q_ROWS * DMODEL];
__device__ float g_KV  [KV_ROWS * 2 * DMODEL];
__device__ float g_attn[Q_ROWS * DMODEL];
__device__ float g_Po[8 * HEADS * N_Q * DH];
__device__ float g_Pm[8 * HEADS * N_Q];
__device__ float g_Pl[8 * HEADS * N_Q];

// ---------------- LayerNorm ----------------
__device__ __forceinline__ void ln_row(const float* __restrict__ xr,
                                       const float* __restrict__ g,
                                       const float* __restrict__ b,
                                       float* __restrict__ out0,
                                       float* __restrict__ out1) {
    int t = threadIdx.x;
    const float4* x4 = (const float4*)xr;
    float4 v = x4[t];
    float s  = v.x + v.y + v.z + v.w;
    float ss = v.x*v.x + v.y*v.y + v.z*v.z + v.w*v.w;
    #pragma unroll
    for (int o = 16; o; o >>= 1) {
        s  += __shfl_xor_sync(0xffffffffu, s,  o);
        ss += __shfl_xor_sync(0xffffffffu, ss, o);
    }
    __shared__ float sb[8], ssb[8];
    if ((t & 31) == 0) { sb[t >> 5] = s; ssb[t >> 5] = ss; }
    __syncthreads();
    float S = 0.f, SS = 0.f;
    #pragma unroll
    for (int i = 0; i < 8; i++) { S += sb[i]; SS += ssb[i]; }
    float mean = S * (1.0f / DMODEL);
    float var  = SS * (1.0f / DMODEL) - mean * mean;
    float rstd = rsqrtf(var + 1e-5f);
    float4 gg = ((const float4*)g)[t];
    float4 bb = ((const float4*)b)[t];
    float4 o;
    o.x = (v.x - mean) * rstd * gg.x + bb.x;
    o.y = (v.y - mean) * rstd * gg.y + bb.y;
    o.z = (v.z - mean) * rstd * gg.z + bb.z;
    o.w = (v.w - mean) * rstd * gg.w + bb.w;
    ((float4*)out0)[t] = o;
    if (out1) ((float4*)out1)[t] = o;
}

__global__ __launch_bounds__(256) void ln_x_kernel(const float* __restrict__ x,
                                                   const float* __restrict__ g,
                                                   const float* __restrict__ b) {
    int row = blockIdx.x;
    int batch = row >> 8;
    int r = row & 255;
    ln_row(x + (size_t)row * DMODEL, g, b,
           g_kvin + (size_t)(batch * CHUNK + r) * DMODEL, nullptr);
}

__global__ __launch_bounds__(256) void ln_lat_kernel(const float* __restrict__ lat,
                                                     const float* __restrict__ g,
                                                     const float* __restrict__ b) {
    int row = blockIdx.x;
    int batch = row >> 6;
    int q = row & 63;
    float* out1 = (batch < B_X)
        ? (g_kvin + (size_t)(batch * CHUNK + N_KV + q) * DMODEL) : nullptr;
    ln_row(lat + (size_t)row * DMODEL, g, b,
           g_latn + (size_t)row * DMODEL, out1);
}

// ---------------- common MMA helpers ----------------
__device__ __forceinline__ unsigned bf2pack(float lo, float hi) {
    __nv_bfloat162 h = __floats2bfloat162_rn(lo, hi);
    return *(unsigned*)&h;
}
__device__ __forceinline__ void ldsm4(unsigned r[4], const void* p) {
    unsigned a = (unsigned)__cvta_generic_to_shared(p);
    asm volatile("ldmatrix.sync.aligned.m8n8.x4.shared.b16 {%0,%1,%2,%3}, [%4];"
                 : "=r"(r[0]), "=r"(r[1]), "=r"(r[2]), "=r"(r[3]) : "r"(a));
}
__device__ __forceinline__ void ldsm4t(unsigned r[4], const void* p) {
    unsigned a = (unsigned)__cvta_generic_to_shared(p);
    asm volatile("ldmatrix.sync.aligned.m8n8.x4.trans.shared.b16 {%0,%1,%2,%3}, [%4];"
                 : "=r"(r[0]), "=r"(r[1]), "=r"(r[2]), "=r"(r[3]) : "r"(a));
}
__device__ __forceinline__ void mma16816(float c[4], const unsigned a[4],
                                         unsigned b0, unsigned b1) {
    asm volatile(
        "mma.sync.aligned.m16n8k16.row.col.f32.bf16.bf16.f32 "
        "{%0,%1,%2,%3},{%4,%5,%6,%7},{%8,%9},{%0,%1,%2,%3};"
        : "+f"(c[0]), "+f"(c[1]), "+f"(c[2]), "+f"(c[3])
        : "r"(a[0]), "r"(a[1]), "r"(a[2]), "r"(a[3]), "r"(b0), "r"(b1));
}
// split a float pair into hi/lo bf16x2 words
__device__ __forceinline__ void pack_hilo(float p0, float p1, unsigned& hi, unsigned& lo) {
    __nv_bfloat16 h0 = __float2bfloat16_rn(p0);
    __nv_bfloat16 h1 = __float2bfloat16_rn(p1);
    hi = bf2pack(__bfloat162float(h0), __bfloat162float(h1));
    lo = bf2pack(p0 - __bfloat162float(h0), p1 - __bfloat162float(h1));
}

// ---------------- bf16x3 double-buffered tensor-core GEMM ----------------
#define GBM 128
#define GBN 128
#define GBK 32
#define PA  40      // A smem pitch (bf16)
#define PB  136     // B smem pitch (bf16)
#define A_SZ (GBM * PA)                // 5120
#define B_SZ (GBK * PB)                // 4352
#define ABUF (2 * A_SZ + 2 * B_SZ)     // elems per buffer = 18944
#define GEMM_SMEM (2 * ABUF * (int)sizeof(__nv_bfloat16))  // 75776 B

__global__ __launch_bounds__(256) void gemm_bf16x3_kernel(
        const float* __restrict__ A, const float* __restrict__ B,
        float* __restrict__ C, int M, int N, int K) {
    extern __shared__ __align__(16) __nv_bfloat16 dsm[];

    int t = threadIdx.x;
    int lane = t & 31, w = t >> 5;
    int wm = w >> 1, wn = w & 1;
    int m_blk = blockIdx.y * GBM;
    int n_blk = blockIdx.x * GBN;

    float c[2][8][4];
    #pragma unroll
    for (int mt = 0; mt < 2; mt++)
        #pragma unroll
        for (int nt = 0; nt < 8; nt++)
            #pragma unroll
            for (int i = 0; i < 4; i++) c[mt][nt][i] = 0.f;

    int am  = t >> 3;
    int ak4 = t & 7;
    int bk  = t >> 5;
    int bn4 = t & 31;

    float4 ra[2][4], rb[2][4];

    auto loadAB = [&](int s, int k0) {
        #pragma unroll
        for (int i = 0; i < 4; i++) {
            int gm = m_blk + am + 32 * i;
            ra[s][i] = (gm < M) ? *(const float4*)(A + (size_t)gm * K + k0 + 4 * ak4)
                                : make_float4(0.f, 0.f, 0.f, 0.f);
            rb[s][i] = *(const float4*)(B + (size_t)(k0 + bk + 8 * i) * N + n_blk + 4 * bn4);
        }
    };
    auto stage = [&](int p, int s) {
        __nv_bfloat16* Ahi = dsm + p * ABUF;
        __nv_bfloat16* Alo = Ahi + A_SZ;
        __nv_bfloat16* Bhi = Alo + A_SZ;
        __nv_bfloat16* Blo = Bhi + B_SZ;
        #pragma unroll
        for (int i = 0; i < 4; i++) {
            float4 v = ra[s][i];
            __nv_bfloat16 hx = __float2bfloat16_rn(v.x);
            __nv_bfloat16 hy = __float2bfloat16_rn(v.y);
            __nv_bfloat16 hz = __float2bfloat16_rn(v.z);
            __nv_bfloat16 hw = __float2bfloat16_rn(v.w);
            int sa = (am + 32 * i) * PA + 4 * ak4;
            *(unsigned*)&Ahi[sa]     = bf2pack(__bfloat162float(hx), __bfloat162float(hy));
            *(unsigned*)&Ahi[sa + 2] = bf2pack(__bfloat162float(hz), __bfloat162float(hw));
            *(unsigned*)&Alo[sa]     = bf2pack(v.x - __bfloat162float(hx), v.y - __bfloat162float(hy));
            *(unsigned*)&Alo[sa + 2] = bf2pack(v.z - __bfloat162float(hz), v.w - __bfloat162float(hw));

            v = rb[s][i];
            hx = __float2bfloat16_rn(v.x); hy = __float2bfloat16_rn(v.y);
            hz = __float2bfloat16_rn(v.z); hw = __float2bfloat16_rn(v.w);
            int sb = (bk + 8 * i) * PB + 4 * bn4;
            *(unsigned*)&Bhi[sb]     = bf2pack(__bfloat162float(hx), __bfloat162float(hy));
            *(unsigned*)&Bhi[sb + 2] = bf2pack(__bfloat162float(hz), __bfloat162float(hw));
            *(unsigned*)&Blo[sb]     = bf2pack(v.x - __bfloat162float(hx), v.y - __bfloat162float(hy));
            *(unsigned*)&Blo[sb + 2] = bf2pack(v.z - __bfloat162float(hz), v.w - __bfloat162float(hw));
        }
    };

    int l7  = lane & 7;
    int l8  = (lane >> 3) & 1;
    int l16 = lane >> 4;
    int nit = K / GBK;

    loadAB(0, 0);
    stage(0, 0);
    if (nit > 1) loadAB(1, GBK);
    __syncthreads();

    for (int it = 0; it < nit; it++) {
        int cur = it & 1;
        if (it + 1 < nit) stage(1 - cur, (it + 1) & 1);
        if (it + 2 < nit) loadAB(it & 1, (it + 2) * GBK);

        const __nv_bfloat16* Ahi = dsm + cur * ABUF;
        const __nv_bfloat16* Alo = Ahi + A_SZ;
        const __nv_bfloat16* Bhi = Alo + A_SZ;
        const __nv_bfloat16* Blo = Bhi + B_SZ;

        #pragma unroll
        for (int ks = 0; ks < GBK; ks += 16) {
            unsigned ah[2][4], al[2][4];
            #pragma unroll
            for (int mt = 0; mt < 2; mt++) {
                int row = wm * 32 + mt * 16 + l7 + 8 * l8;
                int kc  = ks + 8 * l16;
                ldsm4(ah[mt], &Ahi[row * PA + kc]);
                ldsm4(al[mt], &Alo[row * PA + kc]);
            }
            unsigned bh[4][4], bl[4][4];
            #pragma unroll
            for (int ng = 0; ng < 4; ng++) {
                int krow = ks + l7 + 8 * l8;
                int ncol = wn * 64 + ng * 16 + 8 * l16;
                ldsm4t(bh[ng], &Bhi[krow * PB + ncol]);
                ldsm4t(bl[ng], &Blo[krow * PB + ncol]);
            }
            #pragma unroll
            for (int mt = 0; mt < 2; mt++)
                #pragma unroll
                for (int nt = 0; nt < 8; nt++) {
                    int ng = nt >> 1, hf = (nt & 1) << 1;
                    mma16816(c[mt][nt], ah[mt], bh[ng][hf], bh[ng][hf + 1]);
                    mma16816(c[mt][nt], ah[mt], bl[ng][hf], bl[ng][hf + 1]);
                    mma16816(c[mt][nt], al[mt], bh[ng][hf], bh[ng][hf + 1]);
                }
        }
        __syncthreads();
    }

    int g = lane >> 2, tig = lane & 3;
    #pragma unroll
    for (int mt = 0; mt < 2; mt++)
        #pragma unroll
        for (int nt = 0; nt < 8; nt++) {
            int r0  = m_blk + wm * 32 + mt * 16 + g;
            int col = n_blk + wn * 64 + nt * 8 + 2 * tig;
            if (r0 < M)
                *(float2*)(C + (size_t)r0 * N + col) =
                    make_float2(c[mt][nt][0], c[mt][nt][1]);
            if (r0 + 8 < M)
                *(float2*)(C + (size_t)(r0 + 8) * N + col) =
                    make_float2(c[mt][nt][2], c[mt][nt][3]);
        }
}

// ---------------- tensor-core flash attention ----------------
// grid (16 jobs, 16 heads), 128 threads = 4 warps; warp w owns q-rows w*16..w*16+15.
// Q/K/V staged hi/lo bf16 in smem; S and P*V via 3-plane m16n8k16.
#define PQ 72
#define ATT_SMEM (6 * 64 * PQ * (int)sizeof(__nv_bfloat16))   // 55296 B

__global__ __launch_bounds__(128) void attn_mma_kernel() {
    extern __shared__ __align__(16) __nv_bfloat16 asm_[];
    __nv_bfloat16* Qhi = asm_;
    __nv_bfloat16* Qlo = Qhi + 64 * PQ;
    __nv_bfloat16* Khi = Qlo + 64 * PQ;
    __nv_bfloat16* Klo = Khi + 64 * PQ;
    __nv_bfloat16* Vhi = Klo + 64 * PQ;
    __nv_bfloat16* Vlo = Vhi + 64 * PQ;

    int job = blockIdx.x, h = blockIdx.y;
    int t = threadIdx.x, lane = t & 31, w = t >> 5;
    bool diag = (job < 8);
    int qb = diag ? job : 8;
    int kc = diag ? job : (job - 8);

    int l7 = lane & 7, l8 = (lane >> 3) & 1, l16 = lane >> 4;

    // ---- stage Q (scaled, hi/lo split) ----
    #pragma unroll
    for (int i = 0; i < 8; i++) {
        int idx = t + 128 * i;              // 0..1023
        int r = idx >> 4, c4 = (idx & 15) << 2;
        float4 v = *(const float4*)(g_Q + (size_t)(qb * 64 + r) * DMODEL + h * DH + c4);
        v.x *= SCALE; v.y *= SCALE; v.z *= SCALE; v.w *= SCALE;
        __nv_bfloat16 hx = __float2bfloat16_rn(v.x);
        __nv_bfloat16 hy = __float2bfloat16_rn(v.y);
        __nv_bfloat16 hz = __float2bfloat16_rn(v.z);
        __nv_bfloat16 hw = __float2bfloat16_rn(v.w);
        int sa = r * PQ + c4;
        *(unsigned*)&Qhi[sa]     = bf2pack(__bfloat162float(hx), __bfloat162float(hy));
        *(unsigned*)&Qhi[sa + 2] = bf2pack(__bfloat162float(hz), __bfloat162float(hw));
        *(unsigned*)&Qlo[sa]     = bf2pack(v.x - __bfloat162float(hx), v.y - __bfloat162float(hy));
        *(unsigned*)&Qlo[sa + 2] = bf2pack(v.z - __bfloat162float(hz), v.w - __bfloat162float(hw));
    }
    __syncthreads();

    // ---- load Q fragments (A operand, rows w*16..w*16+15) ----
    unsigned qh[4][4], ql[4][4];
    #pragma unroll
    for (int ks = 0; ks < 4; ks++) {
        int row = w * 16 + l7 + 8 * l8;
        int kcc = 16 * ks + 8 * l16;
        ldsm4(qh[ks], &Qhi[row * PQ + kcc]);
        ldsm4(ql[ks], &Qlo[row * PQ + kcc]);
    }

    float m0 = -INFINITY, m1 = -INFINITY, l0 = 0.f, l1 = 0.f;
    float o[8][4];
    #pragma unroll
    for (int j = 0; j < 8; j++)
        #pragma unroll
        for (int i = 0; i < 4; i++) o[j][i] = 0.f;

    for (int tile = 0; tile < CHUNK / 64; tile++) {
        int base = kc * CHUNK + tile * 64;

        // ---- stage K/V tile (hi/lo split) ----
        #pragma unroll
        for (int i = 0; i < 8; i++) {
            int idx = t + 128 * i;
            int r = idx >> 4, c4 = (idx & 15) << 2;
            const float* src = g_KV + (size_t)(base + r) * (2 * DMODEL) + h * DH;
            float4 kk = *(const float4*)(src + c4);
            __nv_bfloat16 hx = __float2bfloat16_rn(kk.x);
            __nv_bfloat16 hy = __float2bfloat16_rn(kk.y);
            __nv_bfloat16 hz = __float2bfloat16_rn(kk.z);
            __nv_bfloat16 hw = __float2bfloat16_rn(kk.w);
            int sa = r * PQ + c4;
            *(unsigned*)&Khi[sa]     = bf2pack(__bfloat162float(hx), __bfloat162float(hy));
            *(unsigned*)&Khi[sa + 2] = bf2pack(__bfloat162float(hz), __bfloat162float(hw));
            *(unsigned*)&Klo[sa]     = bf2pack(kk.x - __bfloat162float(hx), kk.y - __bfloat162float(hy));
            *(unsigned*)&Klo[sa + 2] = bf2pack(kk.z - __bfloat162float(hz), kk.w - __bfloat162float(hw));

            float4 vv = *(const float4*)(src + DMODEL + c4);
            hx = __float2bfloat16_rn(vv.x); hy = __float2bfloat16_rn(vv.y);
            hz = __float2bfloat16_rn(vv.z); hw = __float2bfloat16_rn(vv.w);
            *(unsigned*)&Vhi[sa]     = bf2pack(__bfloat162float(hx), __bfloat162float(hy));
            *(unsigned*)&Vhi[sa + 2] = bf2pack(__bfloat162float(hz), __bfloat162float(hw));
            *(unsigned*)&Vlo[sa]     = bf2pack(vv.x - __bfloat162float(hx), vv.y - __bfloat162float(hy));
            *(unsigned*)&Vlo[sa + 2] = bf2pack(vv.z - __bfloat162float(hz), vv.w - __bfloat162float(hw));
        }
        __syncthreads();

        // ---- S = Q K^T (8 n-octets of 8 kv cols), 3 planes ----
        float s[8][4];
        #pragma unroll
        for (int j = 0; j < 8; j++)
            #pragma unroll
            for (int i = 0; i < 4; i++) s[j][i] = 0.f;

        #pragma unroll
        for (int ks = 0; ks < 4; ks++) {
            #pragma unroll
            for (int ng = 0; ng < 4; ng++) {
                unsigned kbh[4], kbl[4];
                int row = 16 * ng + l7 + 8 * l8;
                int kcc = 16 * ks + 8 * l16;
                ldsm4(kbh, &Khi[row * PQ + kcc]);
                ldsm4(kbl, &Klo[row * PQ + kcc]);
                mma16816(s[2 * ng],     qh[ks], kbh[0], kbh[2]);
                mma16816(s[2 * ng],     qh[ks], kbl[0], kbl[2]);
                mma16816(s[2 * ng],     ql[ks], kbh[0], kbh[2]);
                mma16816(s[2 * ng + 1], qh[ks], kbh[1], kbh[3]);
                mma16816(s[2 * ng + 1], qh[ks], kbl[1], kbl[3]);
                mma16816(s[2 * ng + 1], ql[ks], kbh[1], kbh[3]);
            }
        }

        // ---- online softmax (rows g and g+8) ----
        float mx0 = -INFINITY, mx1 = -INFINITY;
        #pragma unroll
        for (int j = 0; j < 8; j++) {
            mx0 = fmaxf(mx0, fmaxf(s[j][0], s[j][1]));
            mx1 = fmaxf(mx1, fmaxf(s[j][2], s[j][3]));
        }
        #pragma unroll
        for (int ofs = 1; ofs <= 2; ofs <<= 1) {
            mx0 = fmaxf(mx0, __shfl_xor_sync(0xffffffffu, mx0, ofs));
            mx1 = fmaxf(mx1, __shfl_xor_sync(0xffffffffu, mx1, ofs));
        }
        float mn0 = fmaxf(m0, mx0), mn1 = fmaxf(m1, mx1);
        float cr0 = __expf(m0 - mn0), cr1 = __expf(m1 - mn1);
        float sum0 = 0.f, sum1 = 0.f;
        #pragma unroll
        for (int j = 0; j < 8; j++) {
            s[j][0] = __expf(s[j][0] - mn0); sum0 += s[j][0];
            s[j][1] = __expf(s[j][1] - mn0); sum0 += s[j][1];
            s[j][2] = __expf(s[j][2] - mn1); sum1 += s[j][2];
            s[j][3] = __expf(s[j][3] - mn1); sum1 += s[j][3];
        }
        #pragma unroll
        for (int ofs = 1; ofs <= 2; ofs <<= 1) {
            sum0 += __shfl_xor_sync(0xffffffffu, sum0, ofs);
            sum1 += __shfl_xor_sync(0xffffffffu, sum1, ofs);
        }
        l0 = l0 * cr0 + sum0;
        l1 = l1 * cr1 + sum1;
        m0 = mn0; m1 = mn1;
        #pragma unroll
        for (int j = 0; j < 8; j++) {
            o[j][0] *= cr0; o[j][1] *= cr0;
            o[j][2] *= cr1; o[j][3] *= cr1;
        }

        // ---- O += P V (k over kv tile in 4 steps of 16), 3 planes ----
        #pragma unroll
        for (int s4 = 0; s4 < 4; s4++) {
            unsigned ph[4], pl[4];
            pack_hilo(s[2 * s4][0],     s[2 * s4][1],     ph[0], pl[0]);
            pack_hilo(s[2 * s4][2],     s[2 * s4][3],     ph[1], pl[1]);
            pack_hilo(s[2 * s4 + 1][0], s[2 * s4 + 1][1], ph[2], pl[2]);
            pack_hilo(s[2 * s4 + 1][2], s[2 * s4 + 1][3], ph[3], pl[3]);
            #pragma unroll
            for (int ng = 0; ng < 4; ng++) {
                unsigned vbh[4], vbl[4];
                int krow = 16 * s4 + l7 + 8 * l8;
                int ncol = 16 * ng + 8 * l16;
                ldsm4t(vbh, &Vhi[krow * PQ + ncol]);
                ldsm4t(vbl, &Vlo[krow * PQ + ncol]);
                mma16816(o[2 * ng],     ph, vbh[0], vbh[1]);
                mma16816(o[2 * ng],     ph, vbl[0], vbl[1]);
                mma16816(o[2 * ng],     pl, vbh[0], vbh[1]);
                mma16816(o[2 * ng + 1], ph, vbh[2], vbh[3]);
                mma16816(o[2 * ng + 1], ph, vbl[2], vbl[3]);
                mma16816(o[2 * ng + 1], pl, vbh[2], vbh[3]);
            }
        }
        __syncthreads();   // buffers reused next tile
    }

    // ---- epilogue ----
    int g = lane >> 2, tig = lane & 3;
    if (diag) {
        float inv0 = 1.f / l0, inv1 = 1.f / l1;
        #pragma unroll
        for (int j = 0; j < 8; j++) {
            int row0 = qb * 64 + w * 16 + g;
            int col  = h * DH + 8 * j + 2 * tig;
            *(float2*)(g_attn + (size_t)row0 * DMODEL + col) =
                make_float2(o[j][0] * inv0, o[j][1] * inv0);
            *(float2*)(g_attn + (size_t)(row0 + 8) * DMODEL + col) =
                make_float2(o[j][2] * inv1, o[j][3] * inv1);
        }
    } else {
        int base = (kc * HEADS + h) * N_Q;
        int r0 = w * 16 + g, r1 = r0 + 8;
        #pragma unroll
        for (int j = 0; j < 8; j++) {
            int col = 8 * j + 2 * tig;
            *(float2*)(g_Po + (size_t)(base + r0) * DH + col) =
                make_float2(o[j][0], o[j][1]);
            *(float2*)(g_Po + (size_t)(base + r1) * DH + col) =
                make_float2(o[j][2], o[j][3]);
        }
        if (tig == 0) {
            g_Pm[base + r0] = m0; g_Pl[base + r0] = l0;
            g_Pm[base + r1] = m1; g_Pl[base + r1] = l1;
        }
    }
}

// combine split-KV partials for batch 8
__global__ __launch_bounds__(64) void attn_reduce_kernel() {
    int h = blockIdx.x, r = blockIdx.y, d = threadIdx.x;
    float mx = -INFINITY;
    #pragma unroll
    for (int c = 0; c < 8; c++)
        mx = fmaxf(mx, g_Pm[(c * HEADS + h) * N_Q + r]);
    float lsum = 0.f, acc = 0.f;
    #pragma unroll
    for (int c = 0; c < 8; c++) {
        float wgt = __expf(g_Pm[(c * HEADS + h) * N_Q + r] - mx);
        lsum += g_Pl[(c * HEADS + h) * N_Q + r] * wgt;
        acc = fmaf(g_Po[(size_t)((c * HEADS + h) * N_Q + r) * DH + d], wgt, acc);
    }
    g_attn[(size_t)(8 * 64 + r) * DMODEL + h * DH + d] = acc / lsum;
}

// ---------------- launch ----------------
extern "C" void kernel_launch(void* const* d_in, const int* in_sizes, int n_in,
                              void* d_out, int out_size) {
    const float* x    = (const float*)d_in[0];
    const float* lat  = (const float*)d_in[1];
    const float* g1   = (const float*)d_in[2];
    const float* b1   = (const float*)d_in[3];
    const float* g2   = (const float*)d_in[4];
    const float* b2   = (const float*)d_in[5];
    const float* Wq   = (const float*)d_in[6];
    const float* Wkv  = (const float*)d_in[7];
    const float* Wout = (const float*)d_in[8];
    float* out = (float*)d_out;

    void *p_latn, *p_kvin, *p_Q, *p_KV, *p_attn;
    cudaGetSymbolAddress(&p_latn, g_latn);
    cudaGetSymbolAddress(&p_kvin, g_kvin);
    cudaGetSymbolAddress(&p_Q,    g_Q);
    cudaGetSymbolAddress(&p_KV,   g_KV);
    cudaGetSymbolAddress(&p_attn, g_attn);

    cudaFuncSetAttribute(gemm_bf16x3_kernel,
                         cudaFuncAttributeMaxDynamicSharedMemorySize, GEMM_SMEM);
    cudaFuncSetAttribute(attn_mma_kernel,
                         cudaFuncAttributeMaxDynamicSharedMemorySize, ATT_SMEM);

    ln_x_kernel<<<B_X * N_KV, 256>>>(x, g1, b1);
    ln_lat_kernel<<<Q_ROWS, 256>>>(lat, g2, b2);

    // Q = latn @ Wq : (576 x 1024) @ (1024 x 1024)
    gemm_bf16x3_kernel<<<dim3(DMODEL / GBN, (Q_ROWS + GBM - 1) / GBM), 256, GEMM_SMEM>>>(
        (const float*)p_latn, Wq, (float*)p_Q, Q_ROWS, DMODEL, DMODEL);

    // KV = kvin @ Wkv : (2560 x 1024) @ (1024 x 2048)
    gemm_bf16x3_kernel<<<dim3(2 * DMODEL / GBN, KV_ROWS / GBM), 256, GEMM_SMEM>>>(
        (const float*)p_kvin, Wkv, (float*)p_KV, KV_ROWS, 2 * DMODEL, DMODEL);

    attn_mma_kernel<<<dim3(16, HEADS), 128, ATT_SMEM>>>();
    attn_reduce_kernel<<<dim3(HEADS, N_Q), 64>>>();

    // out = attn @ Wout : (576 x 1024) @ (1024 x 1024)
    gemm_bf16x3_kernel<<<dim3(DMODEL / GBN, (Q_ROWS + GBM - 1) / GBM), 256, GEMM_SMEM>>>(
        (const float*)p_attn, Wout, out, Q_ROWS, DMODEL, DMODEL);

    (void)in_sizes; (void)n_in; (void)out_size;
}

// round 16
// speedup vs baseline: 1.2698x; 1.2698x over previous
#include <cuda_runtime.h>
#include <cuda_bf16.h>
#include <math.h>

// ---------------- problem constants ----------------
#define DMODEL 1024
#define HEADS  16
#define DH     64
#define B_LAT  9
#define B_X    8
#define N_KV   256
#define N_Q    64
#define CHUNK  (N_KV + N_Q)          // 320
#define KV_ROWS (B_X * CHUNK)        // 2560
#define Q_ROWS  (B_LAT * N_Q)        // 576
#define SCALE   0.125f               // DH^-0.5 applied to Q

// ---------------- scratch ----------------
__device__ float g_kvin[KV_ROWS * DMODEL];
__device__ float g_latn[Q_ROWS * DMODEL];
__device__ float g_Q   [Q_ROWS * DMODEL];
__device__ float g_KV  [KV_ROWS * 2 * DMODEL];
__device__ float g_attn[Q_ROWS * DMODEL];
__device__ float g_Po[8 * HEADS * N_Q * DH];
__device__ float g_Pm[8 * HEADS * N_Q];
__device__ float g_Pl[8 * HEADS * N_Q];

// ---------------- LayerNorm ----------------
__device__ __forceinline__ void ln_row(const float* __restrict__ xr,
                                       const float* __restrict__ g,
                                       const float* __restrict__ b,
                                       float* __restrict__ out0,
                                       float* __restrict__ out1) {
    int t = threadIdx.x;
    const float4* x4 = (const float4*)xr;
    float4 v = x4[t];
    float s  = v.x + v.y + v.z + v.w;
    float ss = v.x*v.x + v.y*v.y + v.z*v.z + v.w*v.w;
    #pragma unroll
    for (int o = 16; o; o >>= 1) {
        s  += __shfl_xor_sync(0xffffffffu, s,  o);
        ss += __shfl_xor_sync(0xffffffffu, ss, o);
    }
    __shared__ float sb[8], ssb[8];
    if ((t & 31) == 0) { sb[t >> 5] = s; ssb[t >> 5] = ss; }
    __syncthreads();
    float S = 0.f, SS = 0.f;
    #pragma unroll
    for (int i = 0; i < 8; i++) { S += sb[i]; SS += ssb[i]; }
    float mean = S * (1.0f / DMODEL);
    float var  = SS * (1.0f / DMODEL) - mean * mean;
    float rstd = rsqrtf(var + 1e-5f);
    float4 gg = ((const float4*)g)[t];
    float4 bb = ((const float4*)b)[t];
    float4 o;
    o.x = (v.x - mean) * rstd * gg.x + bb.x;
    o.y = (v.y - mean) * rstd * gg.y + bb.y;
    o.z = (v.z - mean) * rstd * gg.z + bb.z;
    o.w = (v.w - mean) * rstd * gg.w + bb.w;
    ((float4*)out0)[t] = o;
    if (out1) ((float4*)out1)[t] = o;
}

__global__ __launch_bounds__(256) void ln_x_kernel(const float* __restrict__ x,
                                                   const float* __restrict__ g,
                                                   const float* __restrict__ b) {
    int row = blockIdx.x;
    int batch = row >> 8;
    int r = row & 255;
    ln_row(x + (size_t)row * DMODEL, g, b,
           g_kvin + (size_t)(batch * CHUNK + r) * DMODEL, nullptr);
}

__global__ __launch_bounds__(256) void ln_lat_kernel(const float* __restrict__ lat,
                                                     const float* __restrict__ g,
                                                     const float* __restrict__ b) {
    int row = blockIdx.x;
    int batch = row >> 6;
    int q = row & 63;
    float* out1 = (batch < B_X)
        ? (g_kvin + (size_t)(batch * CHUNK + N_KV + q) * DMODEL) : nullptr;
    ln_row(lat + (size_t)row * DMODEL, g, b,
           g_latn + (size_t)row * DMODEL, out1);
}

// ---------------- common MMA helpers ----------------
__device__ __forceinline__ unsigned bf2pack(float lo, float hi) {
    __nv_bfloat162 h = __floats2bfloat162_rn(lo, hi);
    return *(unsigned*)&h;
}
__device__ __forceinline__ void ldsm4(unsigned r[4], const void* p) {
    unsigned a = (unsigned)__cvta_generic_to_shared(p);
    asm volatile("ldmatrix.sync.aligned.m8n8.x4.shared.b16 {%0,%1,%2,%3}, [%4];"
                 : "=r"(r[0]), "=r"(r[1]), "=r"(r[2]), "=r"(r[3]) : "r"(a));
}
__device__ __forceinline__ void ldsm4t(unsigned r[4], const void* p) {
    unsigned a = (unsigned)__cvta_generic_to_shared(p);
    asm volatile("ldmatrix.sync.aligned.m8n8.x4.trans.shared.b16 {%0,%1,%2,%3}, [%4];"
                 : "=r"(r[0]), "=r"(r[1]), "=r"(r[2]), "=r"(r[3]) : "r"(a));
}
__device__ __forceinline__ void mma16816(float c[4], const unsigned a[4],
                                         unsigned b0, unsigned b1) {
    asm volatile(
        "mma.sync.aligned.m16n8k16.row.col.f32.bf16.bf16.f32 "
        "{%0,%1,%2,%3},{%4,%5,%6,%7},{%8,%9},{%0,%1,%2,%3};"
        : "+f"(c[0]), "+f"(c[1]), "+f"(c[2]), "+f"(c[3])
        : "r"(a[0]), "r"(a[1]), "r"(a[2]), "r"(a[3]), "r"(b0), "r"(b1));
}
// split a float pair into hi/lo bf16x2 words
__device__ __forceinline__ void pack_hilo(float p0, float p1, unsigned& hi, unsigned& lo) {
    __nv_bfloat16 h0 = __float2bfloat16_rn(p0);
    __nv_bfloat16 h1 = __float2bfloat16_rn(p1);
    hi = bf2pack(__bfloat162float(h0), __bfloat162float(h1));
    lo = bf2pack(p0 - __bfloat162float(h0), p1 - __bfloat162float(h1));
}

// ---------------- bf16x3 tensor-core GEMM (R7-validated single-buffer) ----------------
// C[M,N] = A[M,K] @ B[K,N], fp32 in/out, internally hi/lo bf16 split with
// 3 mma planes (hi*hi + hi*lo + lo*hi). N % 128 == 0, K % 32 == 0, M guarded.
#define GBM 128
#define GBN 128
#define GBK 32
#define PA  40    // A smem row pitch in bf16 (80B -> LDSM conflict-free)
#define PB  136   // B smem row pitch in bf16 (272B -> LDSM conflict-free)

__global__ __launch_bounds__(256) void gemm_bf16x3_kernel(
        const float* __restrict__ A, const float* __restrict__ B,
        float* __restrict__ C, int M, int N, int K) {
    __shared__ __align__(16) __nv_bfloat16 sAhi[GBM * PA];
    __shared__ __align__(16) __nv_bfloat16 sAlo[GBM * PA];
    __shared__ __align__(16) __nv_bfloat16 sBhi[GBK * PB];
    __shared__ __align__(16) __nv_bfloat16 sBlo[GBK * PB];

    int t = threadIdx.x;
    int lane = t & 31, w = t >> 5;
    int wm = w >> 1, wn = w & 1;           // 4 x 2 warp grid
    int m_blk = blockIdx.y * GBM;
    int n_blk = blockIdx.x * GBN;

    float c[2][8][4];
    #pragma unroll
    for (int mt = 0; mt < 2; mt++)
        #pragma unroll
        for (int nt = 0; nt < 8; nt++)
            #pragma unroll
            for (int i = 0; i < 4; i++) c[mt][nt][i] = 0.f;

    // per-thread gmem tile coords
    int am  = t >> 3;            // 0..31, A row stride 32 per i
    int ak4 = t & 7;             // float4 col in A tile
    int bk  = t >> 5;            // 0..7, B k-row stride 8 per i
    int bn4 = t & 31;            // float4 col in B tile

    float4 ra[4], rb[4];
    #pragma unroll
    for (int i = 0; i < 4; i++) {
        int gm = m_blk + am + 32 * i;
        ra[i] = (gm < M) ? *(const float4*)(A + (size_t)gm * K + 4 * ak4)
                         : make_float4(0.f, 0.f, 0.f, 0.f);
        rb[i] = *(const float4*)(B + (size_t)(bk + 8 * i) * N + n_blk + 4 * bn4);
    }

    // lane-derived ldmatrix row selectors
    int l7  = lane & 7;
    int l8  = (lane >> 3) & 1;
    int l16 = lane >> 4;

    for (int k0 = 0; k0 < K; k0 += GBK) {
        // ---- stage smem (hi/lo split) ----
        #pragma unroll
        for (int i = 0; i < 4; i++) {
            float4 v = ra[i];
            __nv_bfloat16 hx = __float2bfloat16_rn(v.x);
            __nv_bfloat16 hy = __float2bfloat16_rn(v.y);
            __nv_bfloat16 hz = __float2bfloat16_rn(v.z);
            __nv_bfloat16 hw = __float2bfloat16_rn(v.w);
            int sa = (am + 32 * i) * PA + 4 * ak4;
            *(unsigned*)&sAhi[sa]     = bf2pack(__bfloat162float(hx), __bfloat162float(hy));
            *(unsigned*)&sAhi[sa + 2] = bf2pack(__bfloat162float(hz), __bfloat162float(hw));
            *(unsigned*)&sAlo[sa]     = bf2pack(v.x - __bfloat162float(hx), v.y - __bfloat162float(hy));
            *(unsigned*)&sAlo[sa + 2] = bf2pack(v.z - __bfloat162float(hz), v.w - __bfloat162float(hw));

            v = rb[i];
            hx = __float2bfloat16_rn(v.x); hy = __float2bfloat16_rn(v.y);
            hz = __float2bfloat16_rn(v.z); hw = __float2bfloat16_rn(v.w);
            int sb = (bk + 8 * i) * PB + 4 * bn4;
            *(unsigned*)&sBhi[sb]     = bf2pack(__bfloat162float(hx), __bfloat162float(hy));
            *(unsigned*)&sBhi[sb + 2] = bf2pack(__bfloat162float(hz), __bfloat162float(hw));
            *(unsigned*)&sBlo[sb]     = bf2pack(v.x - __bfloat162float(hx), v.y - __bfloat162float(hy));
            *(unsigned*)&sBlo[sb + 2] = bf2pack(v.z - __bfloat162float(hz), v.w - __bfloat162float(hw));
        }
        __syncthreads();

        // ---- prefetch next k-block into registers ----
        if (k0 + GBK < K) {
            #pragma unroll
            for (int i = 0; i < 4; i++) {
                int gm = m_blk + am + 32 * i;
                ra[i] = (gm < M) ? *(const float4*)(A + (size_t)gm * K + k0 + GBK + 4 * ak4)
                                 : make_float4(0.f, 0.f, 0.f, 0.f);
                rb[i] = *(const float4*)(B + (size_t)(k0 + GBK + bk + 8 * i) * N + n_blk + 4 * bn4);
            }
        }

        // ---- compute: two k16 steps ----
        #pragma unroll
        for (int ks = 0; ks < GBK; ks += 16) {
            unsigned ah[2][4], al[2][4];
            #pragma unroll
            for (int mt = 0; mt < 2; mt++) {
                int row = wm * 32 + mt * 16 + l7 + 8 * l8;
                int kc  = ks + 8 * l16;
                ldsm4(ah[mt], &sAhi[row * PA + kc]);
                ldsm4(al[mt], &sAlo[row * PA + kc]);
            }
            unsigned bh[4][4], bl[4][4];
            #pragma unroll
            for (int ng = 0; ng < 4; ng++) {
                int krow = ks + l7 + 8 * l8;
                int ncol = wn * 64 + ng * 16 + 8 * l16;
                ldsm4t(bh[ng], &sBhi[krow * PB + ncol]);
                ldsm4t(bl[ng], &sBlo[krow * PB + ncol]);
            }
            #pragma unroll
            for (int mt = 0; mt < 2; mt++)
                #pragma unroll
                for (int nt = 0; nt < 8; nt++) {
                    int ng = nt >> 1, hf = (nt & 1) << 1;
                    mma16816(c[mt][nt], ah[mt], bh[ng][hf], bh[ng][hf + 1]);
                    mma16816(c[mt][nt], ah[mt], bl[ng][hf], bl[ng][hf + 1]);
                    mma16816(c[mt][nt], al[mt], bh[ng][hf], bh[ng][hf + 1]);
                }
        }
        __syncthreads();
    }

    // ---- epilogue ----
    int g = lane >> 2, tig = lane & 3;
    #pragma unroll
    for (int mt = 0; mt < 2; mt++)
        #pragma unroll
        for (int nt = 0; nt < 8; nt++) {
            int r0  = m_blk + wm * 32 + mt * 16 + g;
            int col = n_blk + wn * 64 + nt * 8 + 2 * tig;
            if (r0 < M)
                *(float2*)(C + (size_t)r0 * N + col) =
                    make_float2(c[mt][nt][0], c[mt][nt][1]);
            if (r0 + 8 < M)
                *(float2*)(C + (size_t)(r0 + 8) * N + col) =
                    make_float2(c[mt][nt][2], c[mt][nt][3]);
        }
}

// ---------------- tensor-core flash attention (R12-validated) ----------------
// grid (16 jobs, 16 heads), 128 threads = 4 warps; warp w owns q-rows w*16..w*16+15.
// Q/K/V staged hi/lo bf16 in smem; S and P*V via 3-plane m16n8k16.
#define PQ 72
#define ATT_SMEM (6 * 64 * PQ * (int)sizeof(__nv_bfloat16))   // 55296 B

__global__ __launch_bounds__(128) void attn_mma_kernel() {
    extern __shared__ __align__(16) __nv_bfloat16 asm_[];
    __nv_bfloat16* Qhi = asm_;
    __nv_bfloat16* Qlo = Qhi + 64 * PQ;
    __nv_bfloat16* Khi = Qlo + 64 * PQ;
    __nv_bfloat16* Klo = Khi + 64 * PQ;
    __nv_bfloat16* Vhi = Klo + 64 * PQ;
    __nv_bfloat16* Vlo = Vhi + 64 * PQ;

    int job = blockIdx.x, h = blockIdx.y;
    int t = threadIdx.x, lane = t & 31, w = t >> 5;
    bool diag = (job < 8);
    int qb = diag ? job : 8;
    int kc = diag ? job : (job - 8);

    int l7 = lane & 7, l8 = (lane >> 3) & 1, l16 = lane >> 4;

    // ---- stage Q (scaled, hi/lo split) ----
    #pragma unroll
    for (int i = 0; i < 8; i++) {
        int idx = t + 128 * i;              // 0..1023
        int r = idx >> 4, c4 = (idx & 15) << 2;
        float4 v = *(const float4*)(g_Q + (size_t)(qb * 64 + r) * DMODEL + h * DH + c4);
        v.x *= SCALE; v.y *= SCALE; v.z *= SCALE; v.w *= SCALE;
        __nv_bfloat16 hx = __float2bfloat16_rn(v.x);
        __nv_bfloat16 hy = __float2bfloat16_rn(v.y);
        __nv_bfloat16 hz = __float2bfloat16_rn(v.z);
        __nv_bfloat16 hw = __float2bfloat16_rn(v.w);
        int sa = r * PQ + c4;
        *(unsigned*)&Qhi[sa]     = bf2pack(__bfloat162float(hx), __bfloat162float(hy));
        *(unsigned*)&Qhi[sa + 2] = bf2pack(__bfloat162float(hz), __bfloat162float(hw));
        *(unsigned*)&Qlo[sa]     = bf2pack(v.x - __bfloat162float(hx), v.y - __bfloat162float(hy));
        *(unsigned*)&Qlo[sa + 2] = bf2pack(v.z - __bfloat162float(hz), v.w - __bfloat162float(hw));
    }
    __syncthreads();

    // ---- load Q fragments (A operand, rows w*16..w*16+15) ----
    unsigned qh[4][4], ql[4][4];
    #pragma unroll
    for (int ks = 0; ks < 4; ks++) {
        int row = w * 16 + l7 + 8 * l8;
        int kcc = 16 * ks + 8 * l16;
        ldsm4(qh[ks], &Qhi[row * PQ + kcc]);
        ldsm4(ql[ks], &Qlo[row * PQ + kcc]);
    }

    float m0 = -INFINITY, m1 = -INFINITY, l0 = 0.f, l1 = 0.f;
    float o[8][4];
    #pragma unroll
    for (int j = 0; j < 8; j++)
        #pragma unroll
        for (int i = 0; i < 4; i++) o[j][i] = 0.f;

    for (int tile = 0; tile < CHUNK / 64; tile++) {
        int base = kc * CHUNK + tile * 64;

        // ---- stage K/V tile (hi/lo split) ----
        #pragma unroll
        for (int i = 0; i < 8; i++) {
            int idx = t + 128 * i;
            int r = idx >> 4, c4 = (idx & 15) << 2;
            const float* src = g_KV + (size_t)(base + r) * (2 * DMODEL) + h * DH;
            float4 kk = *(const float4*)(src + c4);
            __nv_bfloat16 hx = __float2bfloat16_rn(kk.x);
            __nv_bfloat16 hy = __float2bfloat16_rn(kk.y);
            __nv_bfloat16 hz = __float2bfloat16_rn(kk.z);
            __nv_bfloat16 hw = __float2bfloat16_rn(kk.w);
            int sa = r * PQ + c4;
            *(unsigned*)&Khi[sa]     = bf2pack(__bfloat162float(hx), __bfloat162float(hy));
            *(unsigned*)&Khi[sa + 2] = bf2pack(__bfloat162float(hz), __bfloat162float(hw));
            *(unsigned*)&Klo[sa]     = bf2pack(kk.x - __bfloat162float(hx), kk.y - __bfloat162float(hy));
            *(unsigned*)&Klo[sa + 2] = bf2pack(kk.z - __bfloat162float(hz), kk.w - __bfloat162float(hw));

            float4 vv = *(const float4*)(src + DMODEL + c4);
            hx = __float2bfloat16_rn(vv.x); hy = __float2bfloat16_rn(vv.y);
            hz = __float2bfloat16_rn(vv.z); hw = __float2bfloat16_rn(vv.w);
            *(unsigned*)&Vhi[sa]     = bf2pack(__bfloat162float(hx), __bfloat162float(hy));
            *(unsigned*)&Vhi[sa + 2] = bf2pack(__bfloat162float(hz), __bfloat162float(hw));
            *(unsigned*)&Vlo[sa]     = bf2pack(vv.x - __bfloat162float(hx), vv.y - __bfloat162float(hy));
            *(unsigned*)&Vlo[sa + 2] = bf2pack(vv.z - __bfloat162float(hz), vv.w - __bfloat162float(hw));
        }
        __syncthreads();

        // ---- S = Q K^T (8 n-octets of 8 kv cols), 3 planes ----
        float s[8][4];
        #pragma unroll
        for (int j = 0; j < 8; j++)
            #pragma unroll
            for (int i = 0; i < 4; i++) s[j][i] = 0.f;

        #pragma unroll
        for (int ks = 0; ks < 4; ks++) {
            #pragma unroll
            for (int ng = 0; ng < 4; ng++) {
                unsigned kbh[4], kbl[4];
                int row = 16 * ng + l7 + 8 * l8;
                int kcc = 16 * ks + 8 * l16;
                ldsm4(kbh, &Khi[row * PQ + kcc]);
                ldsm4(kbl, &Klo[row * PQ + kcc]);
                mma16816(s[2 * ng],     qh[ks], kbh[0], kbh[2]);
                mma16816(s[2 * ng],     qh[ks], kbl[0], kbl[2]);
                mma16816(s[2 * ng],     ql[ks], kbh[0], kbh[2]);
                mma16816(s[2 * ng + 1], qh[ks], kbh[1], kbh[3]);
                mma16816(s[2 * ng + 1], qh[ks], kbl[1], kbl[3]);
                mma16816(s[2 * ng + 1], ql[ks], kbh[1], kbh[3]);
            }
        }

        // ---- online softmax (rows g and g+8) ----
        float mx0 = -INFINITY, mx1 = -INFINITY;
        #pragma unroll
        for (int j = 0; j < 8; j++) {
            mx0 = fmaxf(mx0, fmaxf(s[j][0], s[j][1]));
            mx1 = fmaxf(mx1, fmaxf(s[j][2], s[j][3]));
        }
        #pragma unroll
        for (int ofs = 1; ofs <= 2; ofs <<= 1) {
            mx0 = fmaxf(mx0, __shfl_xor_sync(0xffffffffu, mx0, ofs));
            mx1 = fmaxf(mx1, __shfl_xor_sync(0xffffffffu, mx1, ofs));
        }
        float mn0 = fmaxf(m0, mx0), mn1 = fmaxf(m1, mx1);
        float cr0 = __expf(m0 - mn0), cr1 = __expf(m1 - mn1);
        float sum0 = 0.f, sum1 = 0.f;
        #pragma unroll
        for (int j = 0; j < 8; j++) {
            s[j][0] = __expf(s[j][0] - mn0); sum0 += s[j][0];
            s[j][1] = __expf(s[j][1] - mn0); sum0 += s[j][1];
            s[j][2] = __expf(s[j][2] - mn1); sum1 += s[j][2];
            s[j][3] = __expf(s[j][3] - mn1); sum1 += s[j][3];
        }
        #pragma unroll
        for (int ofs = 1; ofs <= 2; ofs <<= 1) {
            sum0 += __shfl_xor_sync(0xffffffffu, sum0, ofs);
            sum1 += __shfl_xor_sync(0xffffffffu, sum1, ofs);
        }
        l0 = l0 * cr0 + sum0;
        l1 = l1 * cr1 + sum1;
        m0 = mn0; m1 = mn1;
        #pragma unroll
        for (int j = 0; j < 8; j++) {
            o[j][0] *= cr0; o[j][1] *= cr0;
            o[j][2] *= cr1; o[j][3] *= cr1;
        }

        // ---- O += P V (k over kv tile in 4 steps of 16), 3 planes ----
        #pragma unroll
        for (int s4 = 0; s4 < 4; s4++) {
            unsigned ph[4], pl[4];
            pack_hilo(s[2 * s4][0],     s[2 * s4][1],     ph[0], pl[0]);
            pack_hilo(s[2 * s4][2],     s[2 * s4][3],     ph[1], pl[1]);
            pack_hilo(s[2 * s4 + 1][0], s[2 * s4 + 1][1], ph[2], pl[2]);
            pack_hilo(s[2 * s4 + 1][2], s[2 * s4 + 1][3], ph[3], pl[3]);
            #pragma unroll
            for (int ng = 0; ng < 4; ng++) {
                unsigned vbh[4], vbl[4];
                int krow = 16 * s4 + l7 + 8 * l8;
                int ncol = 16 * ng + 8 * l16;
                ldsm4t(vbh, &Vhi[krow * PQ + ncol]);
                ldsm4t(vbl, &Vlo[krow * PQ + ncol]);
                mma16816(o[2 * ng],     ph, vbh[0], vbh[1]);
                mma16816(o[2 * ng],     ph, vbl[0], vbl[1]);
                mma16816(o[2 * ng],     pl, vbh[0], vbh[1]);
                mma16816(o[2 * ng + 1], ph, vbh[2], vbh[3]);
                mma16816(o[2 * ng + 1], ph, vbl[2], vbl[3]);
                mma16816(o[2 * ng + 1], pl, vbh[2], vbh[3]);
            }
        }
        __syncthreads();   // buffers reused next tile
    }

    // ---- epilogue ----
    int g = lane >> 2, tig = lane & 3;
    if (diag) {
        float inv0 = 1.f / l0, inv1 = 1.f / l1;
        #pragma unroll
        for (int j = 0; j < 8; j++) {
            int row0 = qb * 64 + w * 16 + g;
            int col  = h * DH + 8 * j + 2 * tig;
            *(float2*)(g_attn + (size_t)row0 * DMODEL + col) =
                make_float2(o[j][0] * inv0, o[j][1] * inv0);
            *(float2*)(g_attn + (size_t)(row0 + 8) * DMODEL + col) =
                make_float2(o[j][2] * inv1, o[j][3] * inv1);
        }
    } else {
        int base = (kc * HEADS + h) * N_Q;
        int r0 = w * 16 + g, r1 = r0 + 8;
        #pragma unroll
        for (int j = 0; j < 8; j++) {
            int col = 8 * j + 2 * tig;
            *(float2*)(g_Po + (size_t)(base + r0) * DH + col) =
                make_float2(o[j][0], o[j][1]);
            *(float2*)(g_Po + (size_t)(base + r1) * DH + col) =
                make_float2(o[j][2], o[j][3]);
        }
        if (tig == 0) {
            g_Pm[base + r0] = m0; g_Pl[base + r0] = l0;
            g_Pm[base + r1] = m1; g_Pl[base + r1] = l1;
        }
    }
}

// combine split-KV partials for batch 8
__global__ __launch_bounds__(64) void attn_reduce_kernel() {
    int h = blockIdx.x, r = blockIdx.y, d = threadIdx.x;
    float mx = -INFINITY;
    #pragma unroll
    for (int c = 0; c < 8; c++)
        mx = fmaxf(mx, g_Pm[(c * HEADS + h) * N_Q + r]);
    float lsum = 0.f, acc = 0.f;
    #pragma unroll
    for (int c = 0; c < 8; c++) {
        float wgt = __expf(g_Pm[(c * HEADS + h) * N_Q + r] - mx);
        lsum += g_Pl[(c * HEADS + h) * N_Q + r] * wgt;
        acc = fmaf(g_Po[(size_t)((c * HEADS + h) * N_Q + r) * DH + d], wgt, acc);
    }
    g_attn[(size_t)(8 * 64 + r) * DMODEL + h * DH + d] = acc / lsum;
}

// ---------------- launch ----------------
extern "C" void kernel_launch(void* const* d_in, const int* in_sizes, int n_in,
                              void* d_out, int out_size) {
    const float* x    = (const float*)d_in[0];
    const float* lat  = (const float*)d_in[1];
    const float* g1   = (const float*)d_in[2];
    const float* b1   = (const float*)d_in[3];
    const float* g2   = (const float*)d_in[4];
    const float* b2   = (const float*)d_in[5];
    const float* Wq   = (const float*)d_in[6];
    const float* Wkv  = (const float*)d_in[7];
    const float* Wout = (const float*)d_in[8];
    float* out = (float*)d_out;

    void *p_latn, *p_kvin, *p_Q, *p_KV, *p_attn;
    cudaGetSymbolAddress(&p_latn, g_latn);
    cudaGetSymbolAddress(&p_kvin, g_kvin);
    cudaGetSymbolAddress(&p_Q,    g_Q);
    cudaGetSymbolAddress(&p_KV,   g_KV);
    cudaGetSymbolAddress(&p_attn, g_attn);

    cudaFuncSetAttribute(attn_mma_kernel,
                         cudaFuncAttributeMaxDynamicSharedMemorySize, ATT_SMEM);

    ln_x_kernel<<<B_X * N_KV, 256>>>(x, g1, b1);
    ln_lat_kernel<<<Q_ROWS, 256>>>(lat, g2, b2);

    // Q = latn @ Wq : (576 x 1024) @ (1024 x 1024)
    gemm_bf16x3_kernel<<<dim3(DMODEL / GBN, (Q_ROWS + GBM - 1) / GBM), 256>>>(
        (const float*)p_latn, Wq, (float*)p_Q, Q_ROWS, DMODEL, DMODEL);

    // KV = kvin @ Wkv : (2560 x 1024) @ (1024 x 2048)
    gemm_bf16x3_kernel<<<dim3(2 * DMODEL / GBN, KV_ROWS / GBM), 256>>>(
        (const float*)p_kvin, Wkv, (float*)p_KV, KV_ROWS, 2 * DMODEL, DMODEL);

    attn_mma_kernel<<<dim3(16, HEADS), 128, ATT_SMEM>>>();
    attn_reduce_kernel<<<dim3(HEADS, N_Q), 64>>>();

    // out = attn @ Wout : (576 x 1024) @ (1024 x 1024)
    gemm_bf16x3_kernel<<<dim3(DMODEL / GBN, (Q_ROWS + GBM - 1) / GBM), 256>>>(
        (const float*)p_attn, Wout, out, Q_ROWS, DMODEL, DMODEL);

    (void)in_sizes; (void)n_in; (void)out_size;
}

// round 17
// speedup vs baseline: 1.3322x; 1.0491x over previous
#include <cuda_runtime.h>
#include <cuda_bf16.h>
#include <math.h>

// ---------------- problem constants ----------------
#define DMODEL 1024
#define HEADS  16
#define DH     64
#define B_LAT  9
#define B_X    8
#define N_KV   256
#define N_Q    64
#define CHUNK  (N_KV + N_Q)          // 320
#define KV_ROWS (B_X * CHUNK)        // 2560
#define Q_ROWS  (B_LAT * N_Q)        // 576
#define SCALE   0.125f

typedef __nv_bfloat16 bf16;

// ---------------- scratch: hi/lo bf16 planes ----------------
__device__ bf16 g_kvin_h[KV_ROWS * DMODEL],  g_kvin_l[KV_ROWS * DMODEL];
__device__ bf16 g_latn_h[Q_ROWS * DMODEL],   g_latn_l[Q_ROWS * DMODEL];
__device__ bf16 g_Wq_h[DMODEL * DMODEL],     g_Wq_l[DMODEL * DMODEL];
__device__ bf16 g_Wkv_h[DMODEL * 2 * DMODEL], g_Wkv_l[DMODEL * 2 * DMODEL];
__device__ bf16 g_Wout_h[DMODEL * DMODEL],   g_Wout_l[DMODEL * DMODEL];
__device__ bf16 g_Q_h[Q_ROWS * DMODEL],      g_Q_l[Q_ROWS * DMODEL];     // pre-scaled
__device__ bf16 g_KV_h[KV_ROWS * 2 * DMODEL], g_KV_l[KV_ROWS * 2 * DMODEL];
__device__ bf16 g_attn_h[Q_ROWS * DMODEL],   g_attn_l[Q_ROWS * DMODEL];
__device__ float g_Po[8 * HEADS * N_Q * DH];
__device__ float g_Pm[8 * HEADS * N_Q];
__device__ float g_Pl[8 * HEADS * N_Q];

// ---------------- helpers ----------------
__device__ __forceinline__ unsigned bf2pack(float a, float b) {
    __nv_bfloat162 h = __floats2bfloat162_rn(a, b);
    return *(unsigned*)&h;
}
__device__ __forceinline__ void pack_hilo(float p0, float p1, unsigned& hi, unsigned& lo) {
    bf16 h0 = __float2bfloat16_rn(p0);
    bf16 h1 = __float2bfloat16_rn(p1);
    hi = bf2pack(__bfloat162float(h0), __bfloat162float(h1));
    lo = bf2pack(p0 - __bfloat162float(h0), p1 - __bfloat162float(h1));
}
__device__ __forceinline__ void ldsm4(unsigned r[4], const void* p) {
    unsigned a = (unsigned)__cvta_generic_to_shared(p);
    asm volatile("ldmatrix.sync.aligned.m8n8.x4.shared.b16 {%0,%1,%2,%3}, [%4];"
                 : "=r"(r[0]), "=r"(r[1]), "=r"(r[2]), "=r"(r[3]) : "r"(a));
}
__device__ __forceinline__ void ldsm4t(unsigned r[4], const void* p) {
    unsigned a = (unsigned)__cvta_generic_to_shared(p);
    asm volatile("ldmatrix.sync.aligned.m8n8.x4.trans.shared.b16 {%0,%1,%2,%3}, [%4];"
                 : "=r"(r[0]), "=r"(r[1]), "=r"(r[2]), "=r"(r[3]) : "r"(a));
}
__device__ __forceinline__ void mma16816(float c[4], const unsigned a[4],
                                         unsigned b0, unsigned b1) {
    asm volatile(
        "mma.sync.aligned.m16n8k16.row.col.f32.bf16.bf16.f32 "
        "{%0,%1,%2,%3},{%4,%5,%6,%7},{%8,%9},{%0,%1,%2,%3};"
        : "+f"(c[0]), "+f"(c[1]), "+f"(c[2]), "+f"(c[3])
        : "r"(a[0]), "r"(a[1]), "r"(a[2]), "r"(a[3]), "r"(b0), "r"(b1));
}

// ---------------- weight pre-split: fp32 -> hi/lo planes ----------------
__global__ __launch_bounds__(256) void conv_kernel(const float* __restrict__ src,
                                                   bf16* __restrict__ h,
                                                   bf16* __restrict__ l, int n4) {
    int i = blockIdx.x * 256 + threadIdx.x;
    if (i >= n4) return;
    float4 v = ((const float4*)src)[i];
    unsigned h0, l0, h1, l1;
    pack_hilo(v.x, v.y, h0, l0);
    pack_hilo(v.z, v.w, h1, l1);
    *(unsigned*)&h[4 * i]     = h0;
    *(unsigned*)&h[4 * i + 2] = h1;
    *(unsigned*)&l[4 * i]     = l0;
    *(unsigned*)&l[4 * i + 2] = l1;
}

// ---------------- LayerNorm -> planes ----------------
__device__ __forceinline__ void ln_row_p(const float* __restrict__ xr,
                                         const float* __restrict__ g,
                                         const float* __restrict__ b,
                                         bf16* __restrict__ h0, bf16* __restrict__ l0,
                                         bf16* __restrict__ h1, bf16* __restrict__ l1) {
    int t = threadIdx.x;
    float4 v = ((const float4*)xr)[t];
    float s  = v.x + v.y + v.z + v.w;
    float ss = v.x*v.x + v.y*v.y + v.z*v.z + v.w*v.w;
    #pragma unroll
    for (int o = 16; o; o >>= 1) {
        s  += __shfl_xor_sync(0xffffffffu, s,  o);
        ss += __shfl_xor_sync(0xffffffffu, ss, o);
    }
    __shared__ float sb[8], ssb[8];
    if ((t & 31) == 0) { sb[t >> 5] = s; ssb[t >> 5] = ss; }
    __syncthreads();
    float S = 0.f, SS = 0.f;
    #pragma unroll
    for (int i = 0; i < 8; i++) { S += sb[i]; SS += ssb[i]; }
    float mean = S * (1.0f / DMODEL);
    float var  = SS * (1.0f / DMODEL) - mean * mean;
    float rstd = rsqrtf(var + 1e-5f);
    float4 gg = ((const float4*)g)[t];
    float4 bb = ((const float4*)b)[t];
    float4 o;
    o.x = (v.x - mean) * rstd * gg.x + bb.x;
    o.y = (v.y - mean) * rstd * gg.y + bb.y;
    o.z = (v.z - mean) * rstd * gg.z + bb.z;
    o.w = (v.w - mean) * rstd * gg.w + bb.w;
    unsigned ph0, pl0, ph1, pl1;
    pack_hilo(o.x, o.y, ph0, pl0);
    pack_hilo(o.z, o.w, ph1, pl1);
    *(unsigned*)&h0[4 * t]     = ph0;
    *(unsigned*)&h0[4 * t + 2] = ph1;
    *(unsigned*)&l0[4 * t]     = pl0;
    *(unsigned*)&l0[4 * t + 2] = pl1;
    if (h1) {
        *(unsigned*)&h1[4 * t]     = ph0;
        *(unsigned*)&h1[4 * t + 2] = ph1;
        *(unsigned*)&l1[4 * t]     = pl0;
        *(unsigned*)&l1[4 * t + 2] = pl1;
    }
}

__global__ __launch_bounds__(256) void ln_x_kernel(const float* __restrict__ x,
                                                   const float* __restrict__ g,
                                                   const float* __restrict__ b) {
    int row = blockIdx.x;               // 0..2047
    int batch = row >> 8;
    int r = row & 255;
    size_t dst = (size_t)(batch * CHUNK + r) * DMODEL;
    ln_row_p(x + (size_t)row * DMODEL, g, b,
             g_kvin_h + dst, g_kvin_l + dst, nullptr, nullptr);
}

__global__ __launch_bounds__(256) void ln_lat_kernel(const float* __restrict__ lat,
                                                     const float* __restrict__ g,
                                                     const float* __restrict__ b) {
    int row = blockIdx.x;               // 0..575
    int batch = row >> 6;
    int q = row & 63;
    size_t dst0 = (size_t)row * DMODEL;
    bf16 *h1 = nullptr, *l1 = nullptr;
    if (batch < B_X) {
        size_t dst1 = (size_t)(batch * CHUNK + N_KV + q) * DMODEL;
        h1 = g_kvin_h + dst1; l1 = g_kvin_l + dst1;
    }
    ln_row_p(lat + (size_t)row * DMODEL, g, b,
             g_latn_h + dst0, g_latn_l + dst0, h1, l1);
}

// ---------------- bf16x3 tensor-core GEMM on pre-split planes ----------------
// C = A @ B with A[M,K], B[K,N] given as hi/lo planes. Output: fp32 (Cf) or
// scaled hi/lo planes (Ch/Cl). MMA core identical to R7-validated kernel.
#define GBM 128
#define GBN 128
#define GBK 32
#define PA  40
#define PB  136

__global__ __launch_bounds__(256) void gemm_planes_kernel(
        const bf16* __restrict__ Ah, const bf16* __restrict__ Al,
        const bf16* __restrict__ Bh, const bf16* __restrict__ Bl,
        float* __restrict__ Cf, bf16* __restrict__ Ch, bf16* __restrict__ Cl,
        float scale, int M, int N, int K) {
    __shared__ __align__(16) bf16 sAhi[GBM * PA];
    __shared__ __align__(16) bf16 sAlo[GBM * PA];
    __shared__ __align__(16) bf16 sBhi[GBK * PB];
    __shared__ __align__(16) bf16 sBlo[GBK * PB];

    int t = threadIdx.x;
    int lane = t & 31, w = t >> 5;
    int wm = w >> 1, wn = w & 1;
    int m_blk = blockIdx.y * GBM;
    int n_blk = blockIdx.x * GBN;

    float c[2][8][4];
    #pragma unroll
    for (int mt = 0; mt < 2; mt++)
        #pragma unroll
        for (int nt = 0; nt < 8; nt++)
            #pragma unroll
            for (int i = 0; i < 4; i++) c[mt][nt][i] = 0.f;

    // staging coords: A rows 128 x 32k (uint4 = 8 bf16); B 32k x 128n
    int ar  = t >> 2;            // 0..63 (+64)
    int ac8 = (t & 3) * 8;       // k offset
    int br  = t >> 4;            // 0..15 (+16)
    int bc8 = (t & 15) * 8;      // n offset

    uint4 rah[2], ral[2], rbh[2], rbl[2];
    const uint4 z4 = make_uint4(0u, 0u, 0u, 0u);

    auto loadAB = [&](int k0) {
        #pragma unroll
        for (int i = 0; i < 2; i++) {
            int gm = m_blk + ar + 64 * i;
            if (gm < M) {
                rah[i] = *(const uint4*)(Ah + (size_t)gm * K + k0 + ac8);
                ral[i] = *(const uint4*)(Al + (size_t)gm * K + k0 + ac8);
            } else { rah[i] = z4; ral[i] = z4; }
            int gk = k0 + br + 16 * i;
            rbh[i] = *(const uint4*)(Bh + (size_t)gk * N + n_blk + bc8);
            rbl[i] = *(const uint4*)(Bl + (size_t)gk * N + n_blk + bc8);
        }
    };
    auto stage = [&]() {
        #pragma unroll
        for (int i = 0; i < 2; i++) {
            *(uint4*)&sAhi[(ar + 64 * i) * PA + ac8] = rah[i];
            *(uint4*)&sAlo[(ar + 64 * i) * PA + ac8] = ral[i];
            *(uint4*)&sBhi[(br + 16 * i) * PB + bc8] = rbh[i];
            *(uint4*)&sBlo[(br + 16 * i) * PB + bc8] = rbl[i];
        }
    };

    int l7  = lane & 7;
    int l8  = (lane >> 3) & 1;
    int l16 = lane >> 4;

    loadAB(0);

    for (int k0 = 0; k0 < K; k0 += GBK) {
        stage();
        __syncthreads();
        if (k0 + GBK < K) loadAB(k0 + GBK);

        #pragma unroll
        for (int ks = 0; ks < GBK; ks += 16) {
            unsigned ah[2][4], al[2][4];
            #pragma unroll
            for (int mt = 0; mt < 2; mt++) {
                int row = wm * 32 + mt * 16 + l7 + 8 * l8;
                int kc  = ks + 8 * l16;
                ldsm4(ah[mt], &sAhi[row * PA + kc]);
                ldsm4(al[mt], &sAlo[row * PA + kc]);
            }
            unsigned bh[4][4], bl[4][4];
            #pragma unroll
            for (int ng = 0; ng < 4; ng++) {
                int krow = ks + l7 + 8 * l8;
                int ncol = wn * 64 + ng * 16 + 8 * l16;
                ldsm4t(bh[ng], &sBhi[krow * PB + ncol]);
                ldsm4t(bl[ng], &sBlo[krow * PB + ncol]);
            }
            #pragma unroll
            for (int mt = 0; mt < 2; mt++)
                #pragma unroll
                for (int nt = 0; nt < 8; nt++) {
                    int ng = nt >> 1, hf = (nt & 1) << 1;
                    mma16816(c[mt][nt], ah[mt], bh[ng][hf], bh[ng][hf + 1]);
                    mma16816(c[mt][nt], ah[mt], bl[ng][hf], bl[ng][hf + 1]);
                    mma16816(c[mt][nt], al[mt], bh[ng][hf], bh[ng][hf + 1]);
                }
        }
        __syncthreads();
    }

    // ---- epilogue ----
    int g = lane >> 2, tig = lane & 3;
    #pragma unroll
    for (int mt = 0; mt < 2; mt++)
        #pragma unroll
        for (int nt = 0; nt < 8; nt++) {
            int r0  = m_blk + wm * 32 + mt * 16 + g;
            int col = n_blk + wn * 64 + nt * 8 + 2 * tig;
            if (Cf) {
                if (r0 < M)
                    *(float2*)(Cf + (size_t)r0 * N + col) =
                        make_float2(c[mt][nt][0], c[mt][nt][1]);
                if (r0 + 8 < M)
                    *(float2*)(Cf + (size_t)(r0 + 8) * N + col) =
                        make_float2(c[mt][nt][2], c[mt][nt][3]);
            } else {
                unsigned hh, ll;
                if (r0 < M) {
                    pack_hilo(c[mt][nt][0] * scale, c[mt][nt][1] * scale, hh, ll);
                    *(unsigned*)&Ch[(size_t)r0 * N + col] = hh;
                    *(unsigned*)&Cl[(size_t)r0 * N + col] = ll;
                }
                if (r0 + 8 < M) {
                    pack_hilo(c[mt][nt][2] * scale, c[mt][nt][3] * scale, hh, ll);
                    *(unsigned*)&Ch[(size_t)(r0 + 8) * N + col] = hh;
                    *(unsigned*)&Cl[(size_t)(r0 + 8) * N + col] = ll;
                }
            }
        }
}

// ---------------- tensor-core flash attention on pre-split planes ----------------
#define PQ 72
#define ATT_SMEM (6 * 64 * PQ * (int)sizeof(bf16))   // 55296 B

__global__ __launch_bounds__(128) void attn_mma_kernel() {
    extern __shared__ __align__(16) bf16 asm_[];
    bf16* Qhi = asm_;
    bf16* Qlo = Qhi + 64 * PQ;
    bf16* Khi = Qlo + 64 * PQ;
    bf16* Klo = Khi + 64 * PQ;
    bf16* Vhi = Klo + 64 * PQ;
    bf16* Vlo = Vhi + 64 * PQ;

    int job = blockIdx.x, h = blockIdx.y;
    int t = threadIdx.x, lane = t & 31, w = t >> 5;
    bool diag = (job < 8);
    int qb = diag ? job : 8;
    int kc = diag ? job : (job - 8);

    int l7 = lane & 7, l8 = (lane >> 3) & 1, l16 = lane >> 4;

    // ---- stage Q (pure copy of pre-scaled planes) ----
    #pragma unroll
    for (int i = 0; i < 4; i++) {
        int idx = t + 128 * i;              // 0..511
        int r = idx >> 3, c8 = (idx & 7) * 8;
        size_t src = (size_t)(qb * 64 + r) * DMODEL + h * DH + c8;
        int sa = r * PQ + c8;
        *(uint4*)&Qhi[sa] = *(const uint4*)(g_Q_h + src);
        *(uint4*)&Qlo[sa] = *(const uint4*)(g_Q_l + src);
    }
    __syncthreads();

    unsigned qh[4][4], ql[4][4];
    #pragma unroll
    for (int ks = 0; ks < 4; ks++) {
        int row = w * 16 + l7 + 8 * l8;
        int kcc = 16 * ks + 8 * l16;
        ldsm4(qh[ks], &Qhi[row * PQ + kcc]);
        ldsm4(ql[ks], &Qlo[row * PQ + kcc]);
    }

    float m0 = -INFINITY, m1 = -INFINITY, l0 = 0.f, l1 = 0.f;
    float o[8][4];
    #pragma unroll
    for (int j = 0; j < 8; j++)
        #pragma unroll
        for (int i = 0; i < 4; i++) o[j][i] = 0.f;

    for (int tile = 0; tile < CHUNK / 64; tile++) {
        int base = kc * CHUNK + tile * 64;

        // ---- stage K/V (pure copies) ----
        #pragma unroll
        for (int i = 0; i < 4; i++) {
            int idx = t + 128 * i;
            int r = idx >> 3, c8 = (idx & 7) * 8;
            size_t srow = (size_t)(base + r) * (2 * DMODEL) + h * DH;
            int sa = r * PQ + c8;
            *(uint4*)&Khi[sa] = *(const uint4*)(g_KV_h + srow + c8);
            *(uint4*)&Klo[sa] = *(const uint4*)(g_KV_l + srow + c8);
            *(uint4*)&Vhi[sa] = *(const uint4*)(g_KV_h + srow + DMODEL + c8);
            *(uint4*)&Vlo[sa] = *(const uint4*)(g_KV_l + srow + DMODEL + c8);
        }
        __syncthreads();

        // ---- S = Q K^T, 3 planes ----
        float s[8][4];
        #pragma unroll
        for (int j = 0; j < 8; j++)
            #pragma unroll
            for (int i = 0; i < 4; i++) s[j][i] = 0.f;

        #pragma unroll
        for (int ks = 0; ks < 4; ks++) {
            #pragma unroll
            for (int ng = 0; ng < 4; ng++) {
                unsigned kbh[4], kbl[4];
                int row = 16 * ng + l7 + 8 * l8;
                int kcc = 16 * ks + 8 * l16;
                ldsm4(kbh, &Khi[row * PQ + kcc]);
                ldsm4(kbl, &Klo[row * PQ + kcc]);
                mma16816(s[2 * ng],     qh[ks], kbh[0], kbh[2]);
                mma16816(s[2 * ng],     qh[ks], kbl[0], kbl[2]);
                mma16816(s[2 * ng],     ql[ks], kbh[0], kbh[2]);
                mma16816(s[2 * ng + 1], qh[ks], kbh[1], kbh[3]);
                mma16816(s[2 * ng + 1], qh[ks], kbl[1], kbl[3]);
                mma16816(s[2 * ng + 1], ql[ks], kbh[1], kbh[3]);
            }
        }

        // ---- online softmax (rows g and g+8) ----
        float mx0 = -INFINITY, mx1 = -INFINITY;
        #pragma unroll
        for (int j = 0; j < 8; j++) {
            mx0 = fmaxf(mx0, fmaxf(s[j][0], s[j][1]));
            mx1 = fmaxf(mx1, fmaxf(s[j][2], s[j][3]));
        }
        #pragma unroll
        for (int ofs = 1; ofs <= 2; ofs <<= 1) {
            mx0 = fmaxf(mx0, __shfl_xor_sync(0xffffffffu, mx0, ofs));
            mx1 = fmaxf(mx1, __shfl_xor_sync(0xffffffffu, mx1, ofs));
        }
        float mn0 = fmaxf(m0, mx0), mn1 = fmaxf(m1, mx1);
        float cr0 = __expf(m0 - mn0), cr1 = __expf(m1 - mn1);
        float sum0 = 0.f, sum1 = 0.f;
        #pragma unroll
        for (int j = 0; j < 8; j++) {
            s[j][0] = __expf(s[j][0] - mn0); sum0 += s[j][0];
            s[j][1] = __expf(s[j][1] - mn0); sum0 += s[j][1];
            s[j][2] = __expf(s[j][2] - mn1); sum1 += s[j][2];
            s[j][3] = __expf(s[j][3] - mn1); sum1 += s[j][3];
        }
        #pragma unroll
        for (int ofs = 1; ofs <= 2; ofs <<= 1) {
            sum0 += __shfl_xor_sync(0xffffffffu, sum0, ofs);
            sum1 += __shfl_xor_sync(0xffffffffu, sum1, ofs);
        }
        l0 = l0 * cr0 + sum0;
        l1 = l1 * cr1 + sum1;
        m0 = mn0; m1 = mn1;
        #pragma unroll
        for (int j = 0; j < 8; j++) {
            o[j][0] *= cr0; o[j][1] *= cr0;
            o[j][2] *= cr1; o[j][3] *= cr1;
        }

        // ---- O += P V, 3 planes ----
        #pragma unroll
        for (int s4 = 0; s4 < 4; s4++) {
            unsigned ph[4], pl[4];
            pack_hilo(s[2 * s4][0],     s[2 * s4][1],     ph[0], pl[0]);
            pack_hilo(s[2 * s4][2],     s[2 * s4][3],     ph[1], pl[1]);
            pack_hilo(s[2 * s4 + 1][0], s[2 * s4 + 1][1], ph[2], pl[2]);
            pack_hilo(s[2 * s4 + 1][2], s[2 * s4 + 1][3], ph[3], pl[3]);
            #pragma unroll
            for (int ng = 0; ng < 4; ng++) {
                unsigned vbh[4], vbl[4];
                int krow = 16 * s4 + l7 + 8 * l8;
                int ncol = 16 * ng + 8 * l16;
                ldsm4t(vbh, &Vhi[krow * PQ + ncol]);
                ldsm4t(vbl, &Vlo[krow * PQ + ncol]);
                mma16816(o[2 * ng],     ph, vbh[0], vbh[1]);
                mma16816(o[2 * ng],     ph, vbl[0], vbl[1]);
                mma16816(o[2 * ng],     pl, vbh[0], vbh[1]);
                mma16816(o[2 * ng + 1], ph, vbh[2], vbh[3]);
                mma16816(o[2 * ng + 1], ph, vbl[2], vbl[3]);
                mma16816(o[2 * ng + 1], pl, vbh[2], vbh[3]);
            }
        }
        __syncthreads();
    }

    // ---- epilogue ----
    int g = lane >> 2, tig = lane & 3;
    if (diag) {
        float inv0 = 1.f / l0, inv1 = 1.f / l1;
        #pragma unroll
        for (int j = 0; j < 8; j++) {
            int row0 = qb * 64 + w * 16 + g;
            int col  = h * DH + 8 * j + 2 * tig;
            unsigned hh, ll;
            pack_hilo(o[j][0] * inv0, o[j][1] * inv0, hh, ll);
            *(unsigned*)&g_attn_h[(size_t)row0 * DMODEL + col] = hh;
            *(unsigned*)&g_attn_l[(size_t)row0 * DMODEL + col] = ll;
            pack_hilo(o[j][2] * inv1, o[j][3] * inv1, hh, ll);
            *(unsigned*)&g_attn_h[(size_t)(row0 + 8) * DMODEL + col] = hh;
            *(unsigned*)&g_attn_l[(size_t)(row0 + 8) * DMODEL + col] = ll;
        }
    } else {
        int base = (kc * HEADS + h) * N_Q;
        int r0 = w * 16 + g, r1 = r0 + 8;
        #pragma unroll
        for (int j = 0; j < 8; j++) {
            int col = 8 * j + 2 * tig;
            *(float2*)(g_Po + (size_t)(base + r0) * DH + col) =
                make_float2(o[j][0], o[j][1]);
            *(float2*)(g_Po + (size_t)(base + r1) * DH + col) =
                make_float2(o[j][2], o[j][3]);
        }
        if (tig == 0) {
            g_Pm[base + r0] = m0; g_Pl[base + r0] = l0;
            g_Pm[base + r1] = m1; g_Pl[base + r1] = l1;
        }
    }
}

// combine split-KV partials for batch 8 -> attn planes
__global__ __launch_bounds__(64) void attn_reduce_kernel() {
    int h = blockIdx.x, r = blockIdx.y, d = threadIdx.x;
    float mx = -INFINITY;
    #pragma unroll
    for (int c = 0; c < 8; c++)
        mx = fmaxf(mx, g_Pm[(c * HEADS + h) * N_Q + r]);
    float lsum = 0.f, acc = 0.f;
    #pragma unroll
    for (int c = 0; c < 8; c++) {
        float wgt = __expf(g_Pm[(c * HEADS + h) * N_Q + r] - mx);
        lsum += g_Pl[(c * HEADS + h) * N_Q + r] * wgt;
        acc = fmaf(g_Po[(size_t)((c * HEADS + h) * N_Q + r) * DH + d], wgt, acc);
    }
    float v = acc / lsum;
    bf16 hi = __float2bfloat16_rn(v);
    bf16 lo = __float2bfloat16_rn(v - __bfloat162float(hi));
    size_t dst = (size_t)(8 * 64 + r) * DMODEL + h * DH + d;
    g_attn_h[dst] = hi;
    g_attn_l[dst] = lo;
}

// ---------------- launch ----------------
extern "C" void kernel_launch(void* const* d_in, const int* in_sizes, int n_in,
                              void* d_out, int out_size) {
    const float* x    = (const float*)d_in[0];
    const float* lat  = (const float*)d_in[1];
    const float* g1   = (const float*)d_in[2];
    const float* b1   = (const float*)d_in[3];
    const float* g2   = (const float*)d_in[4];
    const float* b2   = (const float*)d_in[5];
    const float* Wq   = (const float*)d_in[6];
    const float* Wkv  = (const float*)d_in[7];
    const float* Wout = (const float*)d_in[8];
    float* out = (float*)d_out;

    void *p_kvin_h, *p_kvin_l, *p_latn_h, *p_latn_l;
    void *p_Wq_h, *p_Wq_l, *p_Wkv_h, *p_Wkv_l, *p_Wout_h, *p_Wout_l;
    void *p_Q_h, *p_Q_l, *p_KV_h, *p_KV_l, *p_attn_h, *p_attn_l;
    cudaGetSymbolAddress(&p_kvin_h, g_kvin_h);  cudaGetSymbolAddress(&p_kvin_l, g_kvin_l);
    cudaGetSymbolAddress(&p_latn_h, g_latn_h);  cudaGetSymbolAddress(&p_latn_l, g_latn_l);
    cudaGetSymbolAddress(&p_Wq_h, g_Wq_h);      cudaGetSymbolAddress(&p_Wq_l, g_Wq_l);
    cudaGetSymbolAddress(&p_Wkv_h, g_Wkv_h);    cudaGetSymbolAddress(&p_Wkv_l, g_Wkv_l);
    cudaGetSymbolAddress(&p_Wout_h, g_Wout_h);  cudaGetSymbolAddress(&p_Wout_l, g_Wout_l);
    cudaGetSymbolAddress(&p_Q_h, g_Q_h);        cudaGetSymbolAddress(&p_Q_l, g_Q_l);
    cudaGetSymbolAddress(&p_KV_h, g_KV_h);      cudaGetSymbolAddress(&p_KV_l, g_KV_l);
    cudaGetSymbolAddress(&p_attn_h, g_attn_h);  cudaGetSymbolAddress(&p_attn_l, g_attn_l);

    cudaFuncSetAttribute(attn_mma_kernel,
                         cudaFuncAttributeMaxDynamicSharedMemorySize, ATT_SMEM);

    // weight pre-split (graph-replayed each run; ~6 us total)
    conv_kernel<<<(DMODEL * DMODEL / 4 + 255) / 256, 256>>>(
        Wq, (bf16*)p_Wq_h, (bf16*)p_Wq_l, DMODEL * DMODEL / 4);
    conv_kernel<<<(DMODEL * 2 * DMODEL / 4 + 255) / 256, 256>>>(
        Wkv, (bf16*)p_Wkv_h, (bf16*)p_Wkv_l, DMODEL * 2 * DMODEL / 4);
    conv_kernel<<<(DMODEL * DMODEL / 4 + 255) / 256, 256>>>(
        Wout, (bf16*)p_Wout_h, (bf16*)p_Wout_l, DMODEL * DMODEL / 4);

    ln_x_kernel<<<B_X * N_KV, 256>>>(x, g1, b1);
    ln_lat_kernel<<<Q_ROWS, 256>>>(lat, g2, b2);

    // Q = latn @ Wq, epilogue scales by SCALE and writes planes
    gemm_planes_kernel<<<dim3(DMODEL / GBN, (Q_ROWS + GBM - 1) / GBM), 256>>>(
        (const bf16*)p_latn_h, (const bf16*)p_latn_l,
        (const bf16*)p_Wq_h, (const bf16*)p_Wq_l,
        nullptr, (bf16*)p_Q_h, (bf16*)p_Q_l, SCALE, Q_ROWS, DMODEL, DMODEL);

    // KV = kvin @ Wkv, planes out
    gemm_planes_kernel<<<dim3(2 * DMODEL / GBN, KV_ROWS / GBM), 256>>>(
        (const bf16*)p_kvin_h, (const bf16*)p_kvin_l,
        (const bf16*)p_Wkv_h, (const bf16*)p_Wkv_l,
        nullptr, (bf16*)p_KV_h, (bf16*)p_KV_l, 1.0f, KV_ROWS, 2 * DMODEL, DMODEL);

    attn_mma_kernel<<<dim3(16, HEADS), 128, ATT_SMEM>>>();
    attn_reduce_kernel<<<dim3(HEADS, N_Q), 64>>>();

    // out = attn @ Wout, fp32 out
    gemm_planes_kernel<<<dim3(DMODEL / GBN, (Q_ROWS + GBM - 1) / GBM), 256>>>(
        (const bf16*)p_attn_h, (const bf16*)p_attn_l,
        (const bf16*)p_Wout_h, (const bf16*)p_Wout_l,
        out, nullptr, nullptr, 1.0f, Q_ROWS, DMODEL, DMODEL);

    (void)in_sizes; (void)n_in; (void)out_size;
}